// round 4
// baseline (speedup 1.0000x reference)
#include <cuda_runtime.h>

// Problem constants (fixed shapes from the reference)
#define BATCH   8
#define CH      8
#define NPIX    262144            // 512*512
#define KSEG    17
#define NG      (NPIX/4)          // float4 / int4 groups per batch = 65536
#define BLOCKS_X 128
#define THREADS  256
#define WARPS    (THREADS/32)
#define NBLOCKS  (BLOCKS_X*BATCH)
#define NPAIR    120              // C(16,2) pairs among segments 1..16

#define DELTA_V 0.5f
#define TWO_DELTA_D 3.0f
#define EPSV 1e-12f

// Scratch (device globals; zero-initialized at module load, and re-zeroed by
// the finalize block at the end of every run so every launch sees zeros).
__device__ float    g_sums[BATCH*KSEG*CH];
__device__ float    g_counts[BATCH*KSEG];
__device__ float    g_pen[BATCH*KSEG];
__device__ uchar4   g_seg[BATCH*NG];
__device__ unsigned g_done;

// ---------------------------------------------------------------------------
// Pass 1: per-(batch,segment) channel sums + counts. Also caches seg id (u8).
// Segment 0 (background / masked-out) never contributes to the loss -> skip.
__global__ __launch_bounds__(THREADS)
void k_accum(const float4* __restrict__ emb,
             const int4*   __restrict__ lab,
             const int4*   __restrict__ msk) {
    const int b    = blockIdx.y;
    const int tid  = threadIdx.x;
    const int warp = tid >> 5;

    __shared__ float acc[WARPS][KSEG*9];   // [warp][seg][c0..c7, count]
    float* accf = &acc[0][0];
    for (int i = tid; i < WARPS*KSEG*9; i += THREADS) accf[i] = 0.f;
    __syncthreads();

    float* wa = acc[warp];

    const int per_block = NG / BLOCKS_X;   // 512
    const int base = blockIdx.x * per_block;
    const float4* embb = emb + (size_t)b * CH * NG;
    const int4*   labb = lab + (size_t)b * NG;
    const int4*   mskb = msk + (size_t)b * NG;
    uchar4*       segb = g_seg + (size_t)b * NG;

    for (int g = base + tid; g < base + per_block; g += THREADS) {
        int4 l = labb[g];
        int4 m = mskb[g];
        int s0 = m.x ? l.x : 0;
        int s1 = m.y ? l.y : 0;
        int s2 = m.z ? l.z : 0;
        int s3 = m.w ? l.w : 0;
        segb[g] = make_uchar4((unsigned char)s0, (unsigned char)s1,
                              (unsigned char)s2, (unsigned char)s3);
        if ((s0 | s1 | s2 | s3) == 0) continue;

        float4 e[CH];
        #pragma unroll
        for (int c = 0; c < CH; c++) e[c] = embb[(size_t)c * NG + g];

        if (s0) {
            float* a = &wa[s0*9];
            #pragma unroll
            for (int c = 0; c < CH; c++) atomicAdd(&a[c], e[c].x);
            atomicAdd(&a[8], 1.f);
        }
        if (s1) {
            float* a = &wa[s1*9];
            #pragma unroll
            for (int c = 0; c < CH; c++) atomicAdd(&a[c], e[c].y);
            atomicAdd(&a[8], 1.f);
        }
        if (s2) {
            float* a = &wa[s2*9];
            #pragma unroll
            for (int c = 0; c < CH; c++) atomicAdd(&a[c], e[c].z);
            atomicAdd(&a[8], 1.f);
        }
        if (s3) {
            float* a = &wa[s3*9];
            #pragma unroll
            for (int c = 0; c < CH; c++) atomicAdd(&a[c], e[c].w);
            atomicAdd(&a[8], 1.f);
        }
    }
    __syncthreads();

    // Reduce warp copies, flush to global
    for (int i = tid; i < KSEG*9; i += THREADS) {
        float v = 0.f;
        #pragma unroll
        for (int w = 0; w < WARPS; w++) v += acc[w][i];
        int s = i / 9, r = i - s*9;
        if (s != 0 && v != 0.f) {
            if (r < 8) atomicAdd(&g_sums[(b*KSEG + s)*CH + r], v);
            else       atomicAdd(&g_counts[b*KSEG + s], v);
        }
    }
}

// ---------------------------------------------------------------------------
// Pass 2: hinged pull penalty per pixel, accumulated per (batch,segment).
// The LAST block to finish also performs the finalize (pull/push reduction)
// and re-zeroes all scratch for the next run.
__global__ __launch_bounds__(THREADS)
void k_pen(const float4* __restrict__ emb, float* __restrict__ out, int out_size) {
    const int b    = blockIdx.y;
    const int tid  = threadIdx.x;
    const int warp = tid >> 5;

    __shared__ float smean[KSEG*CH];
    __shared__ float spen[WARPS][KSEG];

    for (int i = tid; i < KSEG*CH; i += THREADS) {
        int s = i / CH, c = i - s*CH;
        smean[i] = g_sums[(b*KSEG + s)*CH + c] / fmaxf(g_counts[b*KSEG + s], 1.f);
    }
    for (int i = tid; i < WARPS*KSEG; i += THREADS) (&spen[0][0])[i] = 0.f;
    __syncthreads();

    float* wp = spen[warp];

    const int per_block = NG / BLOCKS_X;
    const int base = blockIdx.x * per_block;
    const float4* embb = emb + (size_t)b * CH * NG;
    const uchar4* segb = g_seg + (size_t)b * NG;

    for (int g = base + tid; g < base + per_block; g += THREADS) {
        uchar4 s4 = segb[g];
        if ((s4.x | s4.y | s4.z | s4.w) == 0) continue;

        float4 e[CH];
        #pragma unroll
        for (int c = 0; c < CH; c++) e[c] = embb[(size_t)c * NG + g];

        if (s4.x) {
            float ss = 0.f;
            #pragma unroll
            for (int c = 0; c < CH; c++) { float d = e[c].x - smean[s4.x*CH + c]; ss = fmaf(d, d, ss); }
            float d = sqrtf(fmaxf(ss, EPSV));
            float h = fmaxf(d - DELTA_V, 0.f);
            atomicAdd(&wp[s4.x], h*h);
        }
        if (s4.y) {
            float ss = 0.f;
            #pragma unroll
            for (int c = 0; c < CH; c++) { float d = e[c].y - smean[s4.y*CH + c]; ss = fmaf(d, d, ss); }
            float d = sqrtf(fmaxf(ss, EPSV));
            float h = fmaxf(d - DELTA_V, 0.f);
            atomicAdd(&wp[s4.y], h*h);
        }
        if (s4.z) {
            float ss = 0.f;
            #pragma unroll
            for (int c = 0; c < CH; c++) { float d = e[c].z - smean[s4.z*CH + c]; ss = fmaf(d, d, ss); }
            float d = sqrtf(fmaxf(ss, EPSV));
            float h = fmaxf(d - DELTA_V, 0.f);
            atomicAdd(&wp[s4.z], h*h);
        }
        if (s4.w) {
            float ss = 0.f;
            #pragma unroll
            for (int c = 0; c < CH; c++) { float d = e[c].w - smean[s4.w*CH + c]; ss = fmaf(d, d, ss); }
            float d = sqrtf(fmaxf(ss, EPSV));
            float h = fmaxf(d - DELTA_V, 0.f);
            atomicAdd(&wp[s4.w], h*h);
        }
    }
    __syncthreads();

    for (int i = tid; i < KSEG; i += THREADS) {
        float v = 0.f;
        #pragma unroll
        for (int w = 0; w < WARPS; w++) v += spen[w][i];
        if (i != 0 && v != 0.f) atomicAdd(&g_pen[b*KSEG + i], v);
    }

    // ---- last-block finalize ----
    __threadfence();
    __shared__ unsigned s_rank;
    if (tid == 0) s_rank = atomicAdd(&g_done, 1u);
    __syncthreads();
    if (s_rank != NBLOCKS - 1) return;

    __shared__ float s_sum [BATCH*KSEG*CH];   // 1088
    __shared__ float s_cnt [BATCH*KSEG];      // 136
    __shared__ float s_pn  [BATCH*KSEG];      // 136
    __shared__ float s_mean[BATCH*KSEG*CH];   // 1088
    __shared__ float s_pull[BATCH], s_K[BATCH], s_push[BATCH], s_np[BATCH];

    for (int i = tid; i < BATCH*KSEG*CH; i += THREADS) s_sum[i] = g_sums[i];
    for (int i = tid; i < BATCH*KSEG;    i += THREADS) { s_cnt[i] = g_counts[i]; s_pn[i] = g_pen[i]; }
    if (tid < BATCH) { s_pull[tid] = 0.f; s_K[tid] = 0.f; s_push[tid] = 0.f; s_np[tid] = 0.f; }
    __syncthreads();

    // Re-zero scratch for next run (overlaps with compute below; compute uses smem only)
    for (int i = tid; i < BATCH*KSEG*CH; i += THREADS) g_sums[i] = 0.f;
    for (int i = tid; i < BATCH*KSEG;    i += THREADS) { g_counts[i] = 0.f; g_pen[i] = 0.f; }
    if (tid == 0) g_done = 0u;

    // means
    for (int i = tid; i < BATCH*KSEG*CH; i += THREADS) {
        int bs = i / CH;
        s_mean[i] = s_sum[i] / fmaxf(s_cnt[bs], 1.f);
    }
    __syncthreads();

    // pull: one thread per (b, s)
    for (int i = tid; i < BATCH*KSEG; i += THREADS) {
        int s = i % KSEG;
        if (s != 0 && s_cnt[i] > 0.f) {
            int bb = i / KSEG;
            atomicAdd(&s_pull[bb], s_pn[i] / s_cnt[i]);
            atomicAdd(&s_K[bb], 1.f);
        }
    }

    // push: one thread per (b, pair), 8*120 = 960 work items
    for (int pg = tid; pg < BATCH*NPAIR; pg += THREADS) {
        int bb = pg / NPAIR;
        int p  = pg % NPAIR;
        int i = 1, rem = p, row = 15;
        while (rem >= row) { rem -= row; i++; row--; }
        int j = i + 1 + rem;

        if (s_cnt[bb*KSEG + i] > 0.f && s_cnt[bb*KSEG + j] > 0.f) {
            const float* mi = &s_mean[(bb*KSEG + i)*CH];
            const float* mj = &s_mean[(bb*KSEG + j)*CH];
            float ss = 0.f;
            #pragma unroll
            for (int c = 0; c < CH; c++) { float dm = mi[c] - mj[c]; ss = fmaf(dm, dm, ss); }
            float dist = sqrtf(fmaxf(ss, EPSV));
            float hg = fmaxf(TWO_DELTA_D - dist, 0.f);
            atomicAdd(&s_push[bb], hg*hg);
            atomicAdd(&s_np[bb], 1.f);
        }
    }
    __syncthreads();

    if (tid == 0) {
        float nv = 0.f, sp = 0.f, sh = 0.f;
        #pragma unroll
        for (int bb = 0; bb < BATCH; bb++) {
            float K = s_K[bb];
            if (K > 0.f) {
                nv += 1.f;
                sp += s_pull[bb] / K;
                sh += s_push[bb] / fmaxf(s_np[bb], 1.f);
            }
        }
        nv = fmaxf(nv, 1.f);
        out[0] = sp / nv;
        if (out_size > 1) out[1] = sh / nv;
    }
}

// ---------------------------------------------------------------------------
extern "C" void kernel_launch(void* const* d_in, const int* in_sizes, int n_in,
                              void* d_out, int out_size) {
    const float4* emb = (const float4*)d_in[0];
    const int4*   lab = (const int4*)d_in[1];
    const int4*   msk = (const int4*)d_in[2];
    float* out = (float*)d_out;

    dim3 grid(BLOCKS_X, BATCH);
    k_accum<<<grid, THREADS>>>(emb, lab, msk);
    k_pen<<<grid, THREADS>>>(emb, out, out_size);
}

// round 6
// speedup vs baseline: 1.1138x; 1.1138x over previous
#include <cuda_runtime.h>

// Fixed shapes
#define BATCH   8
#define CH      8
#define NPIX    262144            // 512*512
#define KSEG    17
#define NG      (NPIX/4)          // float4 groups per batch = 65536
#define NBLK    512               // persistent grid: must all be co-resident
#define BPB     (NBLK/BATCH)      // 64 blocks per batch
#define GPB     (NG/BPB)          // 1024 groups per block
#define THREADS 256
#define WARPS   (THREADS/32)
#define ITERS   (GPB/THREADS)     // 4 iterations per thread
#define NPAIR   120               // C(16,2)

#define DELTA_V 0.5f
#define TWO_DELTA_D 3.0f
#define EPSV 1e-12f

// Scratch: zero-initialized at module load; finalize block re-zeroes at end of
// every run so each launch (correctness, every graph replay) sees zeros.
__device__ float    g_sums[BATCH*KSEG*CH];
__device__ float    g_counts[BATCH*KSEG];
__device__ float    g_pen[BATCH*KSEG];
__device__ unsigned g_bar0;
__device__ unsigned g_bar1;

__global__ __launch_bounds__(THREADS, 4)
void k_fused(const float4* __restrict__ emb,
             const int4*   __restrict__ lab,
             const int4*   __restrict__ msk,
             float* __restrict__ out, int out_size)
{
    const int tid  = threadIdx.x;
    const int warp = tid >> 5;
    const int bx   = blockIdx.x;
    const int b    = bx >> 6;          // batch
    const int chunk= bx & (BPB-1);     // chunk within batch
    const int base = chunk * GPB;      // group offset within batch

    __shared__ float  acc[WARPS][KSEG*9];   // pass1 per-warp [seg][c0..7,count]
    __shared__ uchar4 sseg[GPB];            // cached seg ids (4KB)
    __shared__ float  smean[KSEG*CH];
    __shared__ float  spen[WARPS][KSEG];
    __shared__ unsigned s_rank;

    const float4* embb = emb + (size_t)b * CH * NG;
    const int4*   labb = lab + (size_t)b * NG;
    const int4*   mskb = msk + (size_t)b * NG;

    // ---------------- Pass 1: per-(b,seg) channel sums + counts --------------
    {
        float* accf = &acc[0][0];
        for (int i = tid; i < WARPS*KSEG*9; i += THREADS) accf[i] = 0.f;
        __syncthreads();
        float* wa = acc[warp];

        #pragma unroll 1
        for (int k = 0; k < ITERS; k++) {
            const int gl = tid + k*THREADS;      // local group
            const int g  = base + gl;

            // issue everything up front (independent loads -> high MLP)
            int4 l = labb[g];
            int4 m = mskb[g];
            float4 e[CH];
            #pragma unroll
            for (int c = 0; c < CH; c++) e[c] = embb[(size_t)c * NG + g];

            int s0 = m.x ? l.x : 0;
            int s1 = m.y ? l.y : 0;
            int s2 = m.z ? l.z : 0;
            int s3 = m.w ? l.w : 0;
            sseg[gl] = make_uchar4((unsigned char)s0, (unsigned char)s1,
                                   (unsigned char)s2, (unsigned char)s3);
            if ((s0 | s1 | s2 | s3) == 0) continue;

            if (s0) {
                float* a = &wa[s0*9];
                #pragma unroll
                for (int c = 0; c < CH; c++) atomicAdd(&a[c], e[c].x);
                atomicAdd(&a[8], 1.f);
            }
            if (s1) {
                float* a = &wa[s1*9];
                #pragma unroll
                for (int c = 0; c < CH; c++) atomicAdd(&a[c], e[c].y);
                atomicAdd(&a[8], 1.f);
            }
            if (s2) {
                float* a = &wa[s2*9];
                #pragma unroll
                for (int c = 0; c < CH; c++) atomicAdd(&a[c], e[c].z);
                atomicAdd(&a[8], 1.f);
            }
            if (s3) {
                float* a = &wa[s3*9];
                #pragma unroll
                for (int c = 0; c < CH; c++) atomicAdd(&a[c], e[c].w);
                atomicAdd(&a[8], 1.f);
            }
        }
        __syncthreads();

        // flush warp copies to global
        for (int i = tid; i < KSEG*9; i += THREADS) {
            float v = 0.f;
            #pragma unroll
            for (int w = 0; w < WARPS; w++) v += acc[w][i];
            int s = i / 9, r = i - s*9;
            if (s != 0 && v != 0.f) {
                if (r < 8) atomicAdd(&g_sums[(b*KSEG + s)*CH + r], v);
                else       atomicAdd(&g_counts[b*KSEG + s], v);
            }
        }
    }

    // ---------------- Grid barrier (all NBLK blocks resident) ---------------
    __syncthreads();
    __threadfence();
    if (tid == 0) {
        atomicAdd(&g_bar0, 1u);
        while (*(volatile unsigned*)&g_bar0 < NBLK) { }
    }
    __syncthreads();

    // ---------------- Pass 2: hinged pull penalty (emb from warm L2) --------
    {
        for (int i = tid; i < KSEG*CH; i += THREADS) {
            int s = i / CH, c = i - s*CH;
            smean[i] = g_sums[(b*KSEG + s)*CH + c] / fmaxf(g_counts[b*KSEG + s], 1.f);
        }
        for (int i = tid; i < WARPS*KSEG; i += THREADS) (&spen[0][0])[i] = 0.f;
        __syncthreads();
        float* wp = spen[warp];

        #pragma unroll 1
        for (int k = 0; k < ITERS; k++) {
            const int gl = tid + k*THREADS;
            const int g  = base + gl;

            uchar4 s4 = sseg[gl];
            float4 e[CH];
            #pragma unroll
            for (int c = 0; c < CH; c++) e[c] = embb[(size_t)c * NG + g];
            if ((s4.x | s4.y | s4.z | s4.w) == 0) continue;

            if (s4.x) {
                float ss = 0.f;
                #pragma unroll
                for (int c = 0; c < CH; c++) { float d = e[c].x - smean[s4.x*CH + c]; ss = fmaf(d, d, ss); }
                float d = sqrtf(fmaxf(ss, EPSV));
                float h = fmaxf(d - DELTA_V, 0.f);
                atomicAdd(&wp[s4.x], h*h);
            }
            if (s4.y) {
                float ss = 0.f;
                #pragma unroll
                for (int c = 0; c < CH; c++) { float d = e[c].y - smean[s4.y*CH + c]; ss = fmaf(d, d, ss); }
                float d = sqrtf(fmaxf(ss, EPSV));
                float h = fmaxf(d - DELTA_V, 0.f);
                atomicAdd(&wp[s4.y], h*h);
            }
            if (s4.z) {
                float ss = 0.f;
                #pragma unroll
                for (int c = 0; c < CH; c++) { float d = e[c].z - smean[s4.z*CH + c]; ss = fmaf(d, d, ss); }
                float d = sqrtf(fmaxf(ss, EPSV));
                float h = fmaxf(d - DELTA_V, 0.f);
                atomicAdd(&wp[s4.z], h*h);
            }
            if (s4.w) {
                float ss = 0.f;
                #pragma unroll
                for (int c = 0; c < CH; c++) { float d = e[c].w - smean[s4.w*CH + c]; ss = fmaf(d, d, ss); }
                float d = sqrtf(fmaxf(ss, EPSV));
                float h = fmaxf(d - DELTA_V, 0.f);
                atomicAdd(&wp[s4.w], h*h);
            }
        }
        __syncthreads();

        for (int i = tid; i < KSEG; i += THREADS) {
            float v = 0.f;
            #pragma unroll
            for (int w = 0; w < WARPS; w++) v += spen[w][i];
            if (i != 0 && v != 0.f) atomicAdd(&g_pen[b*KSEG + i], v);
        }
    }

    // ---------------- Last-block finalize -----------------------------------
    __threadfence();
    if (tid == 0) s_rank = atomicAdd(&g_bar1, 1u);
    __syncthreads();
    if (s_rank != NBLK - 1) return;
    __threadfence();   // acquire: see all other blocks' g_pen/g_sums writes

    __shared__ float s_sum [BATCH*KSEG*CH];
    __shared__ float s_cnt [BATCH*KSEG];
    __shared__ float s_pn  [BATCH*KSEG];
    __shared__ float s_mean[BATCH*KSEG*CH];
    __shared__ float s_pull[BATCH], s_K[BATCH], s_push[BATCH], s_np[BATCH];

    for (int i = tid; i < BATCH*KSEG*CH; i += THREADS) s_sum[i] = g_sums[i];
    for (int i = tid; i < BATCH*KSEG;    i += THREADS) { s_cnt[i] = g_counts[i]; s_pn[i] = g_pen[i]; }
    if (tid < BATCH) { s_pull[tid] = 0.f; s_K[tid] = 0.f; s_push[tid] = 0.f; s_np[tid] = 0.f; }
    __syncthreads();

    // re-zero scratch for the next run
    for (int i = tid; i < BATCH*KSEG*CH; i += THREADS) g_sums[i] = 0.f;
    for (int i = tid; i < BATCH*KSEG;    i += THREADS) { g_counts[i] = 0.f; g_pen[i] = 0.f; }

    for (int i = tid; i < BATCH*KSEG*CH; i += THREADS) {
        int bs = i / CH;
        s_mean[i] = s_sum[i] / fmaxf(s_cnt[bs], 1.f);
    }
    __syncthreads();

    // pull: one thread per (b, s)
    for (int i = tid; i < BATCH*KSEG; i += THREADS) {
        int s = i % KSEG;
        if (s != 0 && s_cnt[i] > 0.f) {
            int bb = i / KSEG;
            atomicAdd(&s_pull[bb], s_pn[i] / s_cnt[i]);
            atomicAdd(&s_K[bb], 1.f);
        }
    }

    // push: one thread per (b, pair)
    for (int pg = tid; pg < BATCH*NPAIR; pg += THREADS) {
        int bb = pg / NPAIR;
        int p  = pg % NPAIR;
        int i = 1, rem = p, row = 15;
        while (rem >= row) { rem -= row; i++; row--; }
        int j = i + 1 + rem;

        if (s_cnt[bb*KSEG + i] > 0.f && s_cnt[bb*KSEG + j] > 0.f) {
            const float* mi = &s_mean[(bb*KSEG + i)*CH];
            const float* mj = &s_mean[(bb*KSEG + j)*CH];
            float ss = 0.f;
            #pragma unroll
            for (int c = 0; c < CH; c++) { float dm = mi[c] - mj[c]; ss = fmaf(dm, dm, ss); }
            float dist = sqrtf(fmaxf(ss, EPSV));
            float hg = fmaxf(TWO_DELTA_D - dist, 0.f);
            atomicAdd(&s_push[bb], hg*hg);
            atomicAdd(&s_np[bb], 1.f);
        }
    }
    __syncthreads();

    if (tid == 0) {
        float nv = 0.f, sp = 0.f, sh = 0.f;
        #pragma unroll
        for (int bb = 0; bb < BATCH; bb++) {
            float K = s_K[bb];
            if (K > 0.f) {
                nv += 1.f;
                sp += s_pull[bb] / K;
                sh += s_push[bb] / fmaxf(s_np[bb], 1.f);
            }
        }
        nv = fmaxf(nv, 1.f);
        out[0] = sp / nv;
        if (out_size > 1) out[1] = sh / nv;
        // reset barrier counters for the next run (all other blocks are done:
        // they arrived at g_bar1, which is after g_bar0)
        g_bar0 = 0u;
        g_bar1 = 0u;
    }
}

// ---------------------------------------------------------------------------
extern "C" void kernel_launch(void* const* d_in, const int* in_sizes, int n_in,
                              void* d_out, int out_size) {
    const float4* emb = (const float4*)d_in[0];
    const int4*   lab = (const int4*)d_in[1];
    const int4*   msk = (const int4*)d_in[2];
    float* out = (float*)d_out;

    k_fused<<<NBLK, THREADS>>>(emb, lab, msk, out, out_size);
}

// round 7
// speedup vs baseline: 1.2223x; 1.0974x over previous
#include <cuda_runtime.h>

// Fixed shapes
#define BATCH   8
#define CH      8
#define NPIX    262144            // 512*512
#define KSEG    17
#define NG      (NPIX/4)          // float4 groups per batch = 65536
#define NBLK    512               // persistent grid: must all be co-resident
#define BPB     (NBLK/BATCH)      // 64 blocks per batch
#define GPB     (NG/BPB)          // 1024 groups per block
#define THREADS 256
#define WARPS   (THREADS/32)
#define ITERS   (GPB/THREADS)     // 4 iterations per thread
#define NPAIR   120               // C(16,2)

#define DELTA_V 0.5f
#define TWO_DELTA_D 3.0f
#define EPSV 1e-12f

// Fixed-point packing: field = (e + 16) * 128, 21 bits per field, 3 per u64.
#define FSCALE 128.f
#define FBIAS  2048.f             // 16 * 128
#define FMASK  0x1FFFFFull

// Scratch: zero-initialized at module load; finalize re-zeroes every run.
__device__ float    g_sums[BATCH*KSEG*CH];
__device__ float    g_counts[BATCH*KSEG];
__device__ float    g_pen[BATCH*KSEG];
__device__ unsigned g_barA[BATCH];   // per-batch pass1 barrier
__device__ unsigned g_bar1;          // global finalize barrier

__device__ __forceinline__ unsigned long long pack3(float a, float b, float c) {
    unsigned qa = __float2uint_rn(fmaf(a, FSCALE, FBIAS));
    unsigned qb = __float2uint_rn(fmaf(b, FSCALE, FBIAS));
    unsigned qc = __float2uint_rn(fmaf(c, FSCALE, FBIAS));
    return (unsigned long long)qa | ((unsigned long long)qb << 21)
         | ((unsigned long long)qc << 42);
}
__device__ __forceinline__ unsigned long long pack2c(float a, float b) {
    unsigned qa = __float2uint_rn(fmaf(a, FSCALE, FBIAS));
    unsigned qb = __float2uint_rn(fmaf(b, FSCALE, FBIAS));
    return (unsigned long long)qa | ((unsigned long long)qb << 21)
         | (1ull << 42);   // count in field 2
}

__global__ __launch_bounds__(THREADS, 4)
void k_fused(const float4* __restrict__ emb,
             const int4*   __restrict__ lab,
             const int4*   __restrict__ msk,
             float* __restrict__ out, int out_size)
{
    const int tid  = threadIdx.x;
    const int warp = tid >> 5;
    const int bx   = blockIdx.x;
    const int b    = bx >> 6;          // batch
    const int chunk= bx & (BPB-1);
    const int base = chunk * GPB;

    __shared__ unsigned long long acc64[WARPS][KSEG*3];  // packed per-warp accum
    __shared__ float smean[KSEG*CH];
    __shared__ float spen[WARPS][KSEG];
    __shared__ unsigned s_rank;

    const float4* embb = emb + (size_t)b * CH * NG;
    const int4*   labb = lab + (size_t)b * NG;
    const int4*   mskb = msk + (size_t)b * NG;

    unsigned seg_pack[ITERS];          // 4 seg ids per iter, packed in a reg

    // -------- Upfront L2 prefetch of this block's entire input --------------
    #pragma unroll
    for (int k = 0; k < ITERS; k++) {
        const int g = base + tid + k*THREADS;
        asm volatile("prefetch.global.L2 [%0];" :: "l"(labb + g));
        asm volatile("prefetch.global.L2 [%0];" :: "l"(mskb + g));
        #pragma unroll
        for (int c = 0; c < CH; c++)
            asm volatile("prefetch.global.L2 [%0];" :: "l"(embb + (size_t)c*NG + g));
    }

    // ---------------- Pass 1: packed fixed-point sums + counts --------------
    {
        unsigned long long* accf = &acc64[0][0];
        for (int i = tid; i < WARPS*KSEG*3; i += THREADS) accf[i] = 0ull;
        __syncthreads();
        unsigned long long* wa = acc64[warp];

        #pragma unroll 1
        for (int k = 0; k < ITERS; k++) {
            const int g = base + tid + k*THREADS;

            int4 l = labb[g];
            int4 m = mskb[g];
            float4 e[CH];
            #pragma unroll
            for (int c = 0; c < CH; c++) e[c] = embb[(size_t)c * NG + g];

            int s0 = m.x ? l.x : 0;
            int s1 = m.y ? l.y : 0;
            int s2 = m.z ? l.z : 0;
            int s3 = m.w ? l.w : 0;
            seg_pack[k] = (unsigned)s0 | ((unsigned)s1 << 8)
                        | ((unsigned)s2 << 16) | ((unsigned)s3 << 24);
            if ((s0 | s1 | s2 | s3) == 0) continue;

            if (s0) {
                atomicAdd(&wa[s0*3+0], pack3(e[0].x, e[1].x, e[2].x));
                atomicAdd(&wa[s0*3+1], pack3(e[3].x, e[4].x, e[5].x));
                atomicAdd(&wa[s0*3+2], pack2c(e[6].x, e[7].x));
            }
            if (s1) {
                atomicAdd(&wa[s1*3+0], pack3(e[0].y, e[1].y, e[2].y));
                atomicAdd(&wa[s1*3+1], pack3(e[3].y, e[4].y, e[5].y));
                atomicAdd(&wa[s1*3+2], pack2c(e[6].y, e[7].y));
            }
            if (s2) {
                atomicAdd(&wa[s2*3+0], pack3(e[0].z, e[1].z, e[2].z));
                atomicAdd(&wa[s2*3+1], pack3(e[3].z, e[4].z, e[5].z));
                atomicAdd(&wa[s2*3+2], pack2c(e[6].z, e[7].z));
            }
            if (s3) {
                atomicAdd(&wa[s3*3+0], pack3(e[0].w, e[1].w, e[2].w));
                atomicAdd(&wa[s3*3+1], pack3(e[3].w, e[4].w, e[5].w));
                atomicAdd(&wa[s3*3+2], pack2c(e[6].w, e[7].w));
            }
        }
        __syncthreads();

        // Flush: unpack fields, remove bias exactly, push float sums to global
        if (tid > 0 && tid < KSEG) {
            const int s = tid;
            unsigned f[9];
            #pragma unroll
            for (int x = 0; x < 9; x++) f[x] = 0u;
            #pragma unroll
            for (int w = 0; w < WARPS; w++) {
                unsigned long long v0 = acc64[w][s*3+0];
                unsigned long long v1 = acc64[w][s*3+1];
                unsigned long long v2 = acc64[w][s*3+2];
                f[0] += (unsigned)(v0 & FMASK); f[1] += (unsigned)((v0>>21) & FMASK); f[2] += (unsigned)((v0>>42) & FMASK);
                f[3] += (unsigned)(v1 & FMASK); f[4] += (unsigned)((v1>>21) & FMASK); f[5] += (unsigned)((v1>>42) & FMASK);
                f[6] += (unsigned)(v2 & FMASK); f[7] += (unsigned)((v2>>21) & FMASK); f[8] += (unsigned)((v2>>42) & FMASK);
            }
            const unsigned cnt = f[8];
            if (cnt) {
                const int bias = (int)(cnt * 2048u);
                #pragma unroll
                for (int c = 0; c < CH; c++) {
                    float v = (float)((int)f[c] - bias) * (1.f/FSCALE);
                    atomicAdd(&g_sums[(b*KSEG + s)*CH + c], v);
                }
                atomicAdd(&g_counts[b*KSEG + s], (float)cnt);
            }
        }
    }

    // ---------------- Per-batch barrier (64 blocks each) ---------------------
    __syncthreads();
    __threadfence();
    if (tid == 0) {
        atomicAdd(&g_barA[b], 1u);
        while (*(volatile unsigned*)&g_barA[b] < BPB) { }
    }
    __syncthreads();
    __threadfence();

    // ---------------- Pass 2: hinged pull penalty (emb from warm L2) --------
    {
        for (int i = tid; i < KSEG*CH; i += THREADS) {
            int s = i / CH, c = i - s*CH;
            smean[i] = g_sums[(b*KSEG + s)*CH + c] / fmaxf(g_counts[b*KSEG + s], 1.f);
        }
        for (int i = tid; i < WARPS*KSEG; i += THREADS) (&spen[0][0])[i] = 0.f;
        __syncthreads();
        float* wp = spen[warp];

        #pragma unroll 1
        for (int k = 0; k < ITERS; k++) {
            const int g = base + tid + k*THREADS;

            if (k + 1 < ITERS) {
                #pragma unroll
                for (int c = 0; c < CH; c++)
                    asm volatile("prefetch.global.L1 [%0];"
                                 :: "l"(embb + (size_t)c*NG + g + THREADS));
            }

            const unsigned sp = seg_pack[k];
            float4 e[CH];
            #pragma unroll
            for (int c = 0; c < CH; c++) e[c] = embb[(size_t)c * NG + g];
            if (sp == 0u) continue;

            const int s0 =  sp        & 0xFF;
            const int s1 = (sp >> 8)  & 0xFF;
            const int s2 = (sp >> 16) & 0xFF;
            const int s3 = (sp >> 24) & 0xFF;

            if (s0) {
                float ss = 0.f;
                #pragma unroll
                for (int c = 0; c < CH; c++) { float d = e[c].x - smean[s0*CH + c]; ss = fmaf(d, d, ss); }
                float d = sqrtf(fmaxf(ss, EPSV));
                float h = fmaxf(d - DELTA_V, 0.f);
                atomicAdd(&wp[s0], h*h);
            }
            if (s1) {
                float ss = 0.f;
                #pragma unroll
                for (int c = 0; c < CH; c++) { float d = e[c].y - smean[s1*CH + c]; ss = fmaf(d, d, ss); }
                float d = sqrtf(fmaxf(ss, EPSV));
                float h = fmaxf(d - DELTA_V, 0.f);
                atomicAdd(&wp[s1], h*h);
            }
            if (s2) {
                float ss = 0.f;
                #pragma unroll
                for (int c = 0; c < CH; c++) { float d = e[c].z - smean[s2*CH + c]; ss = fmaf(d, d, ss); }
                float d = sqrtf(fmaxf(ss, EPSV));
                float h = fmaxf(d - DELTA_V, 0.f);
                atomicAdd(&wp[s2], h*h);
            }
            if (s3) {
                float ss = 0.f;
                #pragma unroll
                for (int c = 0; c < CH; c++) { float d = e[c].w - smean[s3*CH + c]; ss = fmaf(d, d, ss); }
                float d = sqrtf(fmaxf(ss, EPSV));
                float h = fmaxf(d - DELTA_V, 0.f);
                atomicAdd(&wp[s3], h*h);
            }
        }
        __syncthreads();

        for (int i = tid; i < KSEG; i += THREADS) {
            float v = 0.f;
            #pragma unroll
            for (int w = 0; w < WARPS; w++) v += spen[w][i];
            if (i != 0 && v != 0.f) atomicAdd(&g_pen[b*KSEG + i], v);
        }
    }

    // ---------------- Last-block finalize -----------------------------------
    __threadfence();
    if (tid == 0) s_rank = atomicAdd(&g_bar1, 1u);
    __syncthreads();
    if (s_rank != NBLK - 1) return;
    __threadfence();

    __shared__ float s_sum [BATCH*KSEG*CH];
    __shared__ float s_cnt [BATCH*KSEG];
    __shared__ float s_pn  [BATCH*KSEG];
    __shared__ float s_mean[BATCH*KSEG*CH];
    __shared__ float s_pull[BATCH], s_K[BATCH], s_push[BATCH], s_np[BATCH];

    for (int i = tid; i < BATCH*KSEG*CH; i += THREADS) s_sum[i] = g_sums[i];
    for (int i = tid; i < BATCH*KSEG;    i += THREADS) { s_cnt[i] = g_counts[i]; s_pn[i] = g_pen[i]; }
    if (tid < BATCH) { s_pull[tid] = 0.f; s_K[tid] = 0.f; s_push[tid] = 0.f; s_np[tid] = 0.f; }
    __syncthreads();

    // re-zero scratch + barriers for the next run
    for (int i = tid; i < BATCH*KSEG*CH; i += THREADS) g_sums[i] = 0.f;
    for (int i = tid; i < BATCH*KSEG;    i += THREADS) { g_counts[i] = 0.f; g_pen[i] = 0.f; }
    if (tid < BATCH) g_barA[tid] = 0u;
    if (tid == 0)    g_bar1 = 0u;

    for (int i = tid; i < BATCH*KSEG*CH; i += THREADS) {
        int bs = i / CH;
        s_mean[i] = s_sum[i] / fmaxf(s_cnt[bs], 1.f);
    }
    __syncthreads();

    // pull
    for (int i = tid; i < BATCH*KSEG; i += THREADS) {
        int s = i % KSEG;
        if (s != 0 && s_cnt[i] > 0.f) {
            int bb = i / KSEG;
            atomicAdd(&s_pull[bb], s_pn[i] / s_cnt[i]);
            atomicAdd(&s_K[bb], 1.f);
        }
    }

    // push
    for (int pg = tid; pg < BATCH*NPAIR; pg += THREADS) {
        int bb = pg / NPAIR;
        int p  = pg % NPAIR;
        int i = 1, rem = p, row = 15;
        while (rem >= row) { rem -= row; i++; row--; }
        int j = i + 1 + rem;

        if (s_cnt[bb*KSEG + i] > 0.f && s_cnt[bb*KSEG + j] > 0.f) {
            const float* mi = &s_mean[(bb*KSEG + i)*CH];
            const float* mj = &s_mean[(bb*KSEG + j)*CH];
            float ss = 0.f;
            #pragma unroll
            for (int c = 0; c < CH; c++) { float dm = mi[c] - mj[c]; ss = fmaf(dm, dm, ss); }
            float dist = sqrtf(fmaxf(ss, EPSV));
            float hg = fmaxf(TWO_DELTA_D - dist, 0.f);
            atomicAdd(&s_push[bb], hg*hg);
            atomicAdd(&s_np[bb], 1.f);
        }
    }
    __syncthreads();

    if (tid == 0) {
        float nv = 0.f, sp = 0.f, sh = 0.f;
        #pragma unroll
        for (int bb = 0; bb < BATCH; bb++) {
            float K = s_K[bb];
            if (K > 0.f) {
                nv += 1.f;
                sp += s_pull[bb] / K;
                sh += s_push[bb] / fmaxf(s_np[bb], 1.f);
            }
        }
        nv = fmaxf(nv, 1.f);
        out[0] = sp / nv;
        if (out_size > 1) out[1] = sh / nv;
    }
}

// ---------------------------------------------------------------------------
extern "C" void kernel_launch(void* const* d_in, const int* in_sizes, int n_in,
                              void* d_out, int out_size) {
    const float4* emb = (const float4*)d_in[0];
    const int4*   lab = (const int4*)d_in[1];
    const int4*   msk = (const int4*)d_in[2];
    float* out = (float*)d_out;

    k_fused<<<NBLK, THREADS>>>(emb, lab, msk, out, out_size);
}